// round 17
// baseline (speedup 1.0000x reference)
#include <cuda_runtime.h>
#include <cstdint>

#define MT      96
#define NTHR    384
#define YPLANE  (96 * 64)                      // 6144 floats per plane (swizzled, no pad)
#define SMEM_BYTES (4 * YPLANE * 4)            // 98304 (y planes only)

#define A0F 0.011048543456039806f              // 1/sqrt(2*64*64)
#define S1F (0.011048543456039806f * 0.57735026918962576f)

// 8 MB preprocessed weights: 256 chunks (h = 2t+seg) x 8192 floats.
// chunk layout: [0..4095] = dest-0 path tile, [4096..8191] = dest-1..3 path tile,
// each 64x64 tf32 stored in PAIRED mma B-fragment order (LDG.128-loadable).
__device__ __align__(16) uint32_t g_wb[256u * 8192u];

// ---------------- helpers (generic-PTX only) ----------------
static __device__ __forceinline__ uint32_t f2tf(float f) {
    uint32_t r; asm("cvt.rna.tf32.f32 %0, %1;" : "=r"(r) : "f"(f)); return r;
}
static __device__ __forceinline__ void mma8(float& c0, float& c1, float& c2, float& c3,
                                            uint32_t a0, uint32_t a1, uint32_t a2, uint32_t a3,
                                            uint32_t b0, uint32_t b1) {
    asm volatile("mma.sync.aligned.m16n8k8.row.col.f32.tf32.tf32.f32 "
                 "{%0,%1,%2,%3}, {%4,%5,%6,%7}, {%8,%9}, {%0,%1,%2,%3};"
                 : "+f"(c0), "+f"(c1), "+f"(c2), "+f"(c3)
                 : "r"(a0), "r"(a1), "r"(a2), "r"(a3), "r"(b0), "r"(b1));
}
// conflict-free y-plane column swizzle: XOR the k-tile bits with row&7
static __device__ __forceinline__ int swz(int row, int col) {
    return (col & 7) | ((((col >> 3) ^ row) & 7) << 3);
}

// ---------------- prologue: weight -> paired fragment-layout image ----------------
// path: 0=W000(seg0,d0) 1=W110(seg1,d0) 2=W011(seg0,d123) 3=W101(seg1,d123)
__global__ void prep_w(const float* W000a, const float* W110a, const float* W011a, const float* W101a,
                       const float* W000b, const float* W110b, const float* W011b, const float* W101b)
{
    const int b = blockIdx.x;            // 0..511
    const int t = b >> 2, path = b & 3;
    const int tp = t >> 6, u = t & 63;
    const float* W;
    if (tp == 0) W = (path == 0) ? W000a : (path == 1) ? W110a : (path == 2) ? W011a : W101a;
    else         W = (path == 0) ? W000b : (path == 1) ? W110b : (path == 2) ? W011b : W101b;
    const float sc = (path == 0) ? A0F : S1F;
    const float* src = W + (size_t)u * 4096;
    uint32_t* dst = g_wb + (size_t)(2 * t + (path & 1)) * 8192 + (path >= 2 ? 4096 : 0);
    #pragma unroll
    for (int k = 0; k < 16; ++k) {
        const int idx = threadIdx.x + k * 256;      // = v*64 + w
        const int v = idx >> 6, w = idx & 63;
        const int kt = v >> 3, vi = v & 7;
        const int lane = (w & 7) * 4 + (vi >> 1);
        const int nt = w >> 3;
        // paired layout: lane holds 4 consecutive words = fragments (kt,2p) and (kt,2p+1)
        const int pos = ((kt * 4 + (nt >> 1)) * 32 + lane) * 4 + (nt & 1) * 2 + (vi & 1);
        dst[pos] = f2tf(sc * src[idx]);
    }
}

// ---------------- main kernel ----------------
__global__ void __launch_bounds__(NTHR, 1)
fc_tp_mma(const float* __restrict__ e1x, const float* __restrict__ e1y,
          const float* __restrict__ e2x, const float* __restrict__ e2y,
          float* __restrict__ out, int E)
{
    extern __shared__ float sm[];       // planes: y0, y1x, y1y, y1z (tf32, swizzled)
    const int tid = threadIdx.x, lane = tid & 31, wid = tid >> 5;
    const int d = wid & 3, mh = wid >> 2;          // d in 0..3, mh in 0..2
    const int g = lane >> 2, c4 = lane & 3;
    const int eb = blockIdx.x * MT;

    int rows[4];
    #pragma unroll
    for (int m = 0; m < 2; ++m) { rows[2 * m] = eb + mh * 32 + m * 16 + g; rows[2 * m + 1] = rows[2 * m] + 8; }

    float C[2][8][4];
    #pragma unroll
    for (int m = 0; m < 2; ++m)
        #pragma unroll
        for (int n = 0; n < 8; ++n)
            #pragma unroll
            for (int q = 0; q < 4; ++q) C[m][n][q] = 0.f;

    const float* xg = e1x;
    float x0v[4], x1v[4], xxv[4], xyv[4], xzv[4];

    #pragma unroll 1
    for (int t = 0; t < 128; ++t) {
        if ((t & 63) == 0) {
            const int tp = t >> 6;
            xg = tp ? e2x : e1x;
            const float* ygl = tp ? e2y : e1y;
            __syncthreads();
            // stage y0 plane (float4, swizzled cols, tf32-rounded)
            for (int i = tid; i < 96 * 16; i += NTHR) {
                const int r = i >> 4, q = i & 15;
                const int rc = min(eb + r, E - 1);
                const float4 v = *(const float4*)(ygl + (size_t)rc * 256 + q * 4);
                float* dp = sm + r * 64 + swz(r, q * 4);
                dp[0] = __uint_as_float(f2tf(v.x)); dp[1] = __uint_as_float(f2tf(v.y));
                dp[2] = __uint_as_float(f2tf(v.z)); dp[3] = __uint_as_float(f2tf(v.w));
            }
            // stage y1 planes (de-interleave stride-3, swizzled cols, tf32-rounded)
            for (int i = tid; i < 96 * 192; i += NTHR) {
                const int r = i / 192, k = i % 192;
                const int rc = min(eb + r, E - 1);
                const float f = ygl[(size_t)rc * 256 + 64 + k];
                sm[(1 + k % 3) * YPLANE + r * 64 + swz(r, k / 3)] = __uint_as_float(f2tf(f));
            }
            __syncthreads();
        }

        // per-t x scalars (raw f32; HW truncation after product handles tf32)
        {
            const int u = t & 63;
            #pragma unroll
            for (int j = 0; j < 4; ++j) {
                const float* xr = xg + (size_t)min(rows[j], E - 1) * 256;
                x0v[j] = xr[u];
                if (d == 0) { xxv[j] = xr[64 + 3 * u]; xyv[j] = xr[65 + 3 * u]; xzv[j] = xr[66 + 3 * u]; }
                else        x1v[j] = xr[64 + 3 * u + (d - 1)];
            }
        }

        #pragma unroll
        for (int seg = 0; seg < 2; ++seg) {
            // B fragments straight from global (L1-resident: 64KB/t shared by all warps)
            const uint4* bg = (const uint4*)(g_wb + (size_t)(2 * t + seg) * 8192 + (d ? 4096 : 0));

            #pragma unroll
            for (int kt = 0; kt < 8; ++kt) {
                uint32_t bfr[8][2];
                #pragma unroll
                for (int np = 0; np < 4; ++np) {
                    const uint4 q = __ldg(bg + (kt * 4 + np) * 32 + lane);
                    bfr[2 * np][0] = q.x; bfr[2 * np][1] = q.y;
                    bfr[2 * np + 1][0] = q.z; bfr[2 * np + 1][1] = q.w;
                }
                const int vo = kt * 8 + 2 * c4;        // a0 col; a2 = vo+1 (adjacent, same k-tile)
                #pragma unroll
                for (int mt = 0; mt < 2; ++mt) {
                    const int rA = mh * 32 + mt * 16 + g, rB = rA + 8;
                    const int oA = rA * 64 + swz(rA, vo);
                    const int oB = rB * 64 + swz(rB, vo);
                    uint32_t a0, a1, a2, a3;
                    if (d == 0) {
                        if (seg == 0) {                 // A_s = x0 * y0
                            const float2 pA = *(const float2*)(sm + oA);
                            const float2 pB = *(const float2*)(sm + oB);
                            a0 = __float_as_uint(x0v[2 * mt] * pA.x);
                            a2 = __float_as_uint(x0v[2 * mt] * pA.y);
                            a1 = __float_as_uint(x0v[2 * mt + 1] * pB.x);
                            a3 = __float_as_uint(x0v[2 * mt + 1] * pB.y);
                        } else {                        // A_d = sum_i x1i * y1i
                            const float* p1 = sm + YPLANE, *p2 = sm + 2 * YPLANE, *p3 = sm + 3 * YPLANE;
                            float2 qx = *(const float2*)(p1 + oA);
                            float2 qy = *(const float2*)(p2 + oA);
                            float2 qz = *(const float2*)(p3 + oA);
                            a0 = __float_as_uint(xxv[2 * mt] * qx.x + xyv[2 * mt] * qy.x + xzv[2 * mt] * qz.x);
                            a2 = __float_as_uint(xxv[2 * mt] * qx.y + xyv[2 * mt] * qy.y + xzv[2 * mt] * qz.y);
                            qx = *(const float2*)(p1 + oB);
                            qy = *(const float2*)(p2 + oB);
                            qz = *(const float2*)(p3 + oB);
                            a1 = __float_as_uint(xxv[2 * mt + 1] * qx.x + xyv[2 * mt + 1] * qy.x + xzv[2 * mt + 1] * qz.x);
                            a3 = __float_as_uint(xxv[2 * mt + 1] * qx.y + xyv[2 * mt + 1] * qy.y + xzv[2 * mt + 1] * qz.y);
                        }
                    } else {
                        // seg0: a_i = x0 * y1_{d-1} (plane d) ; seg1: c_i = x1_{d-1} * y0 (plane 0)
                        const float* pl = (seg == 0) ? (sm + d * YPLANE) : sm;
                        const float xf0 = (seg == 0) ? x0v[2 * mt] : x1v[2 * mt];
                        const float xf1 = (seg == 0) ? x0v[2 * mt + 1] : x1v[2 * mt + 1];
                        const float2 pA = *(const float2*)(pl + oA);
                        const float2 pB = *(const float2*)(pl + oB);
                        a0 = __float_as_uint(xf0 * pA.x); a2 = __float_as_uint(xf0 * pA.y);
                        a1 = __float_as_uint(xf1 * pB.x); a3 = __float_as_uint(xf1 * pB.y);
                    }
                    #pragma unroll
                    for (int nt = 0; nt < 8; ++nt)
                        mma8(C[mt][nt][0], C[mt][nt][1], C[mt][nt][2], C[mt][nt][3],
                             a0, a1, a2, a3, bfr[nt][0], bfr[nt][1]);
                }
            }
        }
    }

    // ---------------- epilogue ----------------
    #pragma unroll
    for (int mt = 0; mt < 2; ++mt) {
        #pragma unroll
        for (int half = 0; half < 2; ++half) {
            const int e = eb + mh * 32 + mt * 16 + g + half * 8;
            if (e < E) {
                float* orow = out + (size_t)e * 256;
                #pragma unroll
                for (int nt = 0; nt < 8; ++nt) {
                    const float v0 = C[mt][nt][half * 2], v1 = C[mt][nt][half * 2 + 1];
                    const int w = nt * 8 + c4 * 2;
                    if (d == 0) {
                        *(float2*)(orow + w) = make_float2(v0, v1);
                    } else {
                        orow[64 + 3 * w + (d - 1)]       = v0;
                        orow[64 + 3 * (w + 1) + (d - 1)] = v1;
                    }
                }
            }
        }
    }
}

extern "C" void kernel_launch(void* const* d_in, const int* in_sizes, int n_in,
                              void* d_out, int out_size) {
    const float* e1x = (const float*)d_in[0];
    const float* e1y = (const float*)d_in[1];
    const float* e2x = (const float*)d_in[2];
    const float* e2y = (const float*)d_in[3];
    prep_w<<<512, 256>>>((const float*)d_in[4], (const float*)d_in[5],
                         (const float*)d_in[6], (const float*)d_in[7],
                         (const float*)d_in[8], (const float*)d_in[9],
                         (const float*)d_in[10], (const float*)d_in[11]);
    const int E = in_sizes[0] / 256;
    const int grid = (E + MT - 1) / MT;
    cudaFuncSetAttribute(fc_tp_mma, cudaFuncAttributeMaxDynamicSharedMemorySize, SMEM_BYTES);
    fc_tp_mma<<<grid, NTHR, SMEM_BYTES>>>(e1x, e1y, e2x, e2y, (float*)d_out, E);
}